// round 16
// baseline (speedup 1.0000x reference)
#include <cuda_runtime.h>
#include <math.h>

typedef unsigned long long ull;

#define BATCH 512
#define CIN   64
#define LIN   1024
#define COUTC 256
#define K1    32
#define STR1  16
#define TT    63
#define NCLS  2
#define KTOT  2048   // CIN*K1

#define ZTW  68      // transposed-z row width (floats): t=-1..64 pad, 16B-aligned rows
#define BSTR 66      // act/spike row stride in smem

// ---------------- device scratch ----------------
__device__ float g_z1[BATCH * TT * COUTC];        // [n][t][co]
__device__ float g_spk[BATCH * COUTC * 64];       // encoder spikes [n][co][64] (t=63 zero)
__device__ float g_d1s[BATCH * COUTC * 64];       // dense1 spikes  [n][o][64]  (t=63 zero)
__device__ float g_c2wt[COUTC * 3 * COUTC];       // [(ci*3+k)][2*p+h] pairs (p, p+128)
__device__ float g_d1wt[COUTC * COUTC];           // [c][o]
__device__ float g_bn2a[COUTC];

// ---------------- packed fp32x2 helpers ----------------
__device__ __forceinline__ ull pk2(float lo, float hi) {
    ull r; asm("mov.b64 %0, {%1,%2};" : "=l"(r) : "f"(lo), "f"(hi)); return r;
}
__device__ __forceinline__ ull fma2(ull a, ull b, ull c) {
    ull d; asm("fma.rn.f32x2 %0, %1, %2, %3;" : "=l"(d) : "l"(a), "l"(b), "l"(c)); return d;
}
__device__ __forceinline__ float2 upk2(ull v) {
    float2 f; asm("mov.b64 {%0,%1}, %2;" : "=f"(f.x), "=f"(f.y) : "l"(v)); return f;
}

// ---------------- conv1 (im2col GEMM) + BN1 + prep fold (at fma2 floor) ---------
__global__ __launch_bounds__(128, 3)
void conv1_gemm(const float* __restrict__ x,
                const float* __restrict__ c1w,
                const float* __restrict__ c1b,
                const float* __restrict__ bn1g,
                const float* __restrict__ bn1b,
                const float* __restrict__ bn1m,
                const float* __restrict__ bn1v,
                const float* __restrict__ c2w,
                const float* __restrict__ d1w,
                const float* __restrict__ bn2g,
                const float* __restrict__ bn2v)
{
    __shared__ __align__(16) float As[2][16][64];
    __shared__ __align__(16) float Bs[2][16][128];
    const int tid  = threadIdx.x;
    const int lane = tid & 31;
    const int w    = tid >> 5;
    const int mBase = blockIdx.x * 64;
    const int nBase = blockIdx.y * 128;

    if (blockIdx.y == 0) {
        int gid = blockIdx.x * 128 + tid;
        for (int i = gid; i < COUTC * 3 * COUTC; i += 504 * 128) {
            int row = i >> 8, jj = i & 255;
            int ci = row / 3, k = row - 3 * ci;
            int co = (jj >> 1) + 128 * (jj & 1);
            g_c2wt[i] = c2w[(co * COUTC + ci) * 3 + k];
        }
        for (int i = gid; i < COUTC * COUTC; i += 504 * 128) {
            int c = i >> 8, o = i & 255;
            g_d1wt[i] = d1w[o * COUTC + c];
        }
        if (gid < COUTC)
            g_bn2a[gid] = bn2g[gid] / sqrtf(bn2v[gid] + 1e-5f);
    }

    const int warp_m = (w & 1) * 32;
    const int warp_n = (w >> 1) * 64;
    const int g = lane >> 3;
    const int j = lane & 7;

    const int am = tid & 63;
    const int kq = (tid >> 6) * 8;
    const int m_row = mBase + am;
    const int n_idx = m_row / TT;
    const int t_idx = m_row - n_idx * TT;
    const float* xrow = x + ((size_t)n_idx * CIN) * LIN + t_idx * STR1;
    const float* wrow = c1w + (size_t)(nBase + tid) * KTOT;

    ull acc[8][4];
    #pragma unroll
    for (int i = 0; i < 8; i++)
        #pragma unroll
        for (int q = 0; q < 4; q++) acc[i][q] = 0ULL;

    float4 ap0, ap1, bq0, bq1, bq2, bq3;

    #define LOAD_REGS(KB) {                                                    \
        int col = (KB) + kq;                                                   \
        const float* abase = xrow + (size_t)(col >> 5) * LIN + (col & 31);     \
        ap0 = *(const float4*)(abase);                                         \
        ap1 = *(const float4*)(abase + 4);                                     \
        bq0 = *(const float4*)(wrow + (KB));                                   \
        bq1 = *(const float4*)(wrow + (KB) + 4);                               \
        bq2 = *(const float4*)(wrow + (KB) + 8);                               \
        bq3 = *(const float4*)(wrow + (KB) + 12);                              \
    }
    #define STORE_SMEM(B) {                                                    \
        As[B][kq + 0][am] = ap0.x; As[B][kq + 1][am] = ap0.y;                  \
        As[B][kq + 2][am] = ap0.z; As[B][kq + 3][am] = ap0.w;                  \
        As[B][kq + 4][am] = ap1.x; As[B][kq + 5][am] = ap1.y;                  \
        As[B][kq + 6][am] = ap1.z; As[B][kq + 7][am] = ap1.w;                  \
        Bs[B][0][tid]  = bq0.x; Bs[B][1][tid]  = bq0.y;                        \
        Bs[B][2][tid]  = bq0.z; Bs[B][3][tid]  = bq0.w;                        \
        Bs[B][4][tid]  = bq1.x; Bs[B][5][tid]  = bq1.y;                        \
        Bs[B][6][tid]  = bq1.z; Bs[B][7][tid]  = bq1.w;                        \
        Bs[B][8][tid]  = bq2.x; Bs[B][9][tid]  = bq2.y;                        \
        Bs[B][10][tid] = bq2.z; Bs[B][11][tid] = bq2.w;                        \
        Bs[B][12][tid] = bq3.x; Bs[B][13][tid] = bq3.y;                        \
        Bs[B][14][tid] = bq3.z; Bs[B][15][tid] = bq3.w;                        \
    }

    LOAD_REGS(0);
    STORE_SMEM(0);
    __syncthreads();

    int buf = 0;
    for (int kb = 0; kb < KTOT; kb += 16) {
        const bool more = (kb + 16) < KTOT;
        if (more) LOAD_REGS(kb + 16);

        const float (*A)[64]  = As[buf];
        const float (*B)[128] = Bs[buf];
        #pragma unroll
        for (int kk = 0; kk < 16; kk++) {
            float4 x0 = *(const float4*)&A[kk][warp_m + 4 * g];
            float4 x1 = *(const float4*)&A[kk][warp_m + 16 + 4 * g];
            ulonglong2 n0 = *(const ulonglong2*)&B[kk][warp_n + 4 * j];
            ulonglong2 n1 = *(const ulonglong2*)&B[kk][warp_n + 32 + 4 * j];
            ull ap;
            #define FMA_ROW(I, AV)                        \
                ap = pk2(AV, AV);                         \
                acc[I][0] = fma2(ap, n0.x, acc[I][0]);    \
                acc[I][1] = fma2(ap, n0.y, acc[I][1]);    \
                acc[I][2] = fma2(ap, n1.x, acc[I][2]);    \
                acc[I][3] = fma2(ap, n1.y, acc[I][3]);
            FMA_ROW(0, x0.x) FMA_ROW(1, x0.y) FMA_ROW(2, x0.z) FMA_ROW(3, x0.w)
            FMA_ROW(4, x1.x) FMA_ROW(5, x1.y) FMA_ROW(6, x1.z) FMA_ROW(7, x1.w)
            #undef FMA_ROW
        }
        if (more) STORE_SMEM(buf ^ 1);
        __syncthreads();
        buf ^= 1;
    }
    #undef LOAD_REGS
    #undef STORE_SMEM

    float sc[8], bb[8], mm[8], cb[8];
    #pragma unroll
    for (int jj = 0; jj < 8; jj++) {
        int co = nBase + warp_n + ((jj < 4) ? (4 * j + jj) : (32 + 4 * j + jj - 4));
        sc[jj] = bn1g[co] / sqrtf(bn1v[co] + 1e-5f);
        bb[jj] = bn1b[co]; mm[jj] = bn1m[co]; cb[jj] = c1b[co];
    }
    #pragma unroll
    for (int i = 0; i < 8; i++) {
        int m = mBase + warp_m + ((i < 4) ? (4 * g + i) : (16 + 4 * g + i - 4));
        float o_[8];
        #pragma unroll
        for (int q = 0; q < 4; q++) {
            float2 v = upk2(acc[i][q]);
            o_[2 * q] = v.x; o_[2 * q + 1] = v.y;
        }
        #pragma unroll
        for (int jj = 0; jj < 8; jj++) {
            float t1 = (o_[jj] + cb[jj]) - mm[jj];
            o_[jj] = fmaf(t1, sc[jj], bb[jj]);
        }
        float* dst = g_z1 + (size_t)m * COUTC + nBase + warp_n;
        *(float4*)(dst + 4 * j)      = make_float4(o_[0], o_[1], o_[2], o_[3]);
        *(float4*)(dst + 32 + 4 * j) = make_float4(o_[4], o_[5], o_[6], o_[7]);
    }
}

// ---------------- conv2 + BN2 + encoder LIF : grid (n, co-quarter), 2 CTA/SM ----
__global__ __launch_bounds__(256, 2)
void conv2lif_kernel(const float* __restrict__ c2b,
                     const float* __restrict__ bn2b,
                     const float* __restrict__ bn2m)
{
    extern __shared__ float sm[];
    float* zt   = sm;                   // transposed z: [ci][ZTW], float idx = t+1
    float* bufA = sm + COUTC * ZTW;     // [64][BSTR]

    const int n   = blockIdx.x;
    const int q   = blockIdx.y;         // co-quarter 0..3
    const int tid = threadIdx.x;
    const int cog = tid & 31;
    const int th  = tid >> 5;           // 0..7
    const int t0  = th * 8;
    const int p   = q * 32 + cog;       // weight pair index (co=p, co=p+128)

    // ---- zero + fill transposed z (thread = ci; gmem coalesced per t) ----
    {
        float4* z4 = (float4*)zt;
        for (int i = tid; i < COUTC * ZTW / 4; i += 256) z4[i] = make_float4(0, 0, 0, 0);
        __syncthreads();
        const float* src = g_z1 + (size_t)n * (TT * COUTC) + tid;
        float* dst = zt + tid * ZTW + 1;
        #pragma unroll 7
        for (int t = 0; t < TT; t++) dst[t] = src[t * COUTC];
    }
    __syncthreads();

    // ---- conv2: fp32x2 lanes = (co, co+128); 8 t per thread ----
    ull acc[8];
    #pragma unroll
    for (int t = 0; t < 8; t++) acc[t] = 0ULL;
    {
        const ull* wb = (const ull*)g_c2wt;
        ull w0 = wb[p], w1 = wb[128 + p], w2 = wb[256 + p];
        #pragma unroll 2
        for (int ci = 0; ci < COUTC; ci++) {
            const int cin = (ci + 1) & 255;
            const ull* wn = wb + cin * 384;
            ull nw0 = wn[p], nw1 = wn[128 + p], nw2 = wn[256 + p];

            const float* zb = zt + ci * ZTW + t0;     // float idx t0+j == t (t0-1+j) +1
            float4 f0 = *(const float4*)(zb);
            float4 f1 = *(const float4*)(zb + 4);
            float2 f2 = *(const float2*)(zb + 8);
            float zr[10] = {f0.x, f0.y, f0.z, f0.w, f1.x, f1.y, f1.z, f1.w, f2.x, f2.y};
            ull zz[10];
            #pragma unroll
            for (int jj = 0; jj < 10; jj++) zz[jj] = pk2(zr[jj], zr[jj]);
            #pragma unroll
            for (int t = 0; t < 8; t++) {
                acc[t] = fma2(w0, zz[t],     acc[t]);
                acc[t] = fma2(w1, zz[t + 1], acc[t]);
                acc[t] = fma2(w2, zz[t + 2], acc[t]);
            }
            w0 = nw0; w1 = nw1; w2 = nw2;
        }
    }
    // ---- BN2 epilogue into bufA (local rows: cog -> coA, 32+cog -> coB) ----
    {
        const int coA = q * 32 + cog, coB = coA + 128;
        const float cbA = c2b[coA], mA = bn2m[coA], sA = g_bn2a[coA], bA = bn2b[coA];
        const float cbB = c2b[coB], mB = bn2m[coB], sB = g_bn2a[coB], bB = bn2b[coB];
        #pragma unroll
        for (int t = 0; t < 8; t++) {
            float2 v = upk2(acc[t]);
            int tt = t0 + t;                    // tt=63 dummy, zeroed after LIF
            bufA[cog * BSTR + tt]        = fmaf((v.x + cbA) - mA, sA, bA);
            bufA[(32 + cog) * BSTR + tt] = fmaf((v.y + cbB) - mB, sB, bB);
        }
    }
    __syncthreads();

    // ---- encoder CUBA LIF (64 rows) ----
    if (tid < 64) {
        float* row = bufA + tid * BSTR;
        const float cd = (float)(1.0 - 0.9);
        const float vd = (float)(1.0 - 0.9);
        float cur = 0.0f, vol = 0.0f;
        #pragma unroll 1
        for (int t = 0; t < TT; t++) {
            float xv = row[t];
            cur = fmaf(cd, cur, xv);
            vol = fmaf(vd, vol, cur);
            float s = ((vol - 0.3f) >= 0.0f) ? 1.0f : 0.0f;
            row[t] = s;
            vol = vol * (1.0f - s);
        }
        row[TT] = 0.0f;
    }
    __syncthreads();

    // ---- copy spikes to gmem [n][co][64] ----
    for (int idx = tid; idx < 64 * 64; idx += 256) {
        int r = idx >> 6, t = idx & 63;
        int co = (r < 32) ? (q * 32 + r) : (128 + q * 32 + (r - 32));
        g_spk[((size_t)n * COUTC + co) * 64 + t] = bufA[r * BSTR + t];
    }
}

// ---------------- dense1 + LIF : grid (n, o-quarter), 2 CTA/SM ------------------
__global__ __launch_bounds__(256, 2)
void dense1lif_kernel()
{
    extern __shared__ float sm[];
    float* spk  = sm;                   // [256][BSTR]
    float* d1sm = sm + COUTC * BSTR;    // [64][BSTR]

    const int n   = blockIdx.x;
    const int q   = blockIdx.y;         // o-quarter 0..3
    const int tid = threadIdx.x;

    // ---- load spikes (t=63 already zero in gmem) ----
    for (int idx = tid; idx < COUTC * 64; idx += 256) {
        int c = idx >> 6, t = idx & 63;
        spk[c * BSTR + t] = g_spk[(size_t)n * COUTC * 64 + idx];
    }
    __syncthreads();

    // ---- dense1: thread (og, th) -> o = q*64+og, t in [th*16, th*16+16) ----
    {
        const int og = tid & 63;
        const int th = tid >> 6;
        const int t0 = th * 16;
        const int o  = q * 64 + og;
        ull a[8];
        #pragma unroll
        for (int pq = 0; pq < 8; pq++) a[pq] = 0ULL;

        float w = g_d1wt[o];
        #pragma unroll 2
        for (int c = 0; c < COUTC; c++) {
            const int cn = (c + 1) & 255;
            float nw = g_d1wt[cn * COUTC + o];
            ull wp = pk2(w, w);
            const ull* sp = (const ull*)(spk + c * BSTR + t0);
            #pragma unroll
            for (int pq = 0; pq < 8; pq++)
                a[pq] = fma2(wp, sp[pq], a[pq]);
            w = nw;
        }
        ull* dd = (ull*)(d1sm + og * BSTR + t0);
        #pragma unroll
        for (int pq = 0; pq < 8; pq++) dd[pq] = a[pq];
    }
    __syncthreads();

    // ---- dense1 CUBA LIF (64 rows) ----
    if (tid < 64) {
        float* row = d1sm + tid * BSTR;
        const float vdD = (float)(1.0 - 0.1);
        float vol = 0.0f;
        #pragma unroll 1
        for (int t = 0; t < TT; t++) {
            float xv = row[t];
            vol = fmaf(vdD, vol, xv);
            float s = ((vol - 0.1f) >= 0.0f) ? 1.0f : 0.0f;
            row[t] = s;
            vol = vol * (1.0f - s);
        }
        row[TT] = 0.0f;
    }
    __syncthreads();

    for (int idx = tid; idx < 64 * 64; idx += 256) {
        int r = idx >> 6, t = idx & 63;
        g_d1s[((size_t)n * COUTC + q * 64 + r) * 64 + t] = d1sm[r * BSTR + t];
    }
}

// ---------------- dense2 + LIF + output : grid n, 128 thr, gmem-direct ----------
__global__ __launch_bounds__(128, 8)
void dense2_kernel(const float* __restrict__ d2w, float* __restrict__ out)
{
    __shared__ float d2b[128];
    const int n = blockIdx.x;
    const int tid = threadIdx.x;

    if (tid < NCLS * TT) {
        int cls = tid / TT, t = tid - cls * TT;
        const float* w  = d2w + cls * COUTC;
        const float* sp = g_d1s + (size_t)n * COUTC * 64 + t;
        float a = 0.0f;
        #pragma unroll 8
        for (int c = 0; c < COUTC; c++)
            a = fmaf(__ldg(w + c), __ldg(sp + c * 64), a);
        d2b[tid] = a;
    }
    __syncthreads();

    if (tid < NCLS) {
        const float vdD = (float)(1.0 - 0.1);
        float vol = 0.0f;
        const float* rowi = d2b + tid * TT;
        float* rowo = out + (size_t)n * (NCLS * TT) + tid * TT;
        #pragma unroll 1
        for (int t = 0; t < TT; t++) {
            float xv = rowi[t];
            vol = fmaf(vdD, vol, xv);
            float s = ((vol - 0.1f) >= 0.0f) ? 1.0f : 0.0f;
            rowo[t] = s;
            vol = vol * (1.0f - s);
        }
    }
}

// ---------------- launch ----------------
extern "C" void kernel_launch(void* const* d_in, const int* in_sizes, int n_in,
                              void* d_out, int out_size)
{
    const float* x    = (const float*)d_in[0];
    const float* c1w  = (const float*)d_in[1];
    const float* c1b  = (const float*)d_in[2];
    const float* bn1g = (const float*)d_in[3];
    const float* bn1b = (const float*)d_in[4];
    const float* bn1m = (const float*)d_in[5];
    const float* bn1v = (const float*)d_in[6];
    const float* c2w  = (const float*)d_in[7];
    const float* c2b  = (const float*)d_in[8];
    const float* bn2g = (const float*)d_in[9];
    const float* bn2b = (const float*)d_in[10];
    const float* bn2m = (const float*)d_in[11];
    const float* bn2v = (const float*)d_in[12];
    const float* d1w  = (const float*)d_in[13];
    const float* d2w  = (const float*)d_in[14];
    float* out = (float*)d_out;

    const int smemA = (COUTC * ZTW + 64 * BSTR) * (int)sizeof(float);    // 86.5 KB
    const int smemB = (COUTC * BSTR + 64 * BSTR) * (int)sizeof(float);   // 84.5 KB
    cudaFuncSetAttribute(conv2lif_kernel, cudaFuncAttributeMaxDynamicSharedMemorySize, smemA);
    cudaFuncSetAttribute(dense1lif_kernel, cudaFuncAttributeMaxDynamicSharedMemorySize, smemB);

    dim3 g1(504, 2);
    conv1_gemm<<<g1, 128>>>(x, c1w, c1b, bn1g, bn1b, bn1m, bn1v,
                            c2w, d1w, bn2g, bn2v);

    dim3 g2(BATCH, 4);
    conv2lif_kernel<<<g2, 256, smemA>>>(c2b, bn2b, bn2m);

    dense1lif_kernel<<<g2, 256, smemB>>>();

    dense2_kernel<<<BATCH, 128>>>(d2w, out);
}

// round 17
// speedup vs baseline: 1.1487x; 1.1487x over previous
#include <cuda_runtime.h>
#include <math.h>

typedef unsigned long long ull;

#define BATCH 512
#define CIN   64
#define LIN   1024
#define COUTC 256
#define K1    32
#define STR1  16
#define TT    63
#define NCLS  2
#define KTOT  2048   // CIN*K1

#define ZTW  68      // transposed-z row width (floats): t=-1..64 pad, 16B-aligned rows
#define BSTR 66      // act/spike row stride in smem

// ---------------- device scratch ----------------
__device__ float g_z1[BATCH * TT * COUTC];        // [n][t][co]
__device__ float g_spk[BATCH * COUTC * 64];       // encoder spikes [n][co][64] (t=63 zero)
__device__ float g_d1s[BATCH * COUTC * 64];       // dense1 spikes  [n][o][64]  (t=63 zero)
__device__ float g_c2wt[COUTC * 3 * COUTC];       // [(ci*3+k)][2*p+h] pairs (p, p+128)
__device__ float g_d1wt[COUTC * COUTC];           // [c][o]
__device__ float g_bn2a[COUTC];

// ---------------- packed fp32x2 helpers ----------------
__device__ __forceinline__ ull pk2(float lo, float hi) {
    ull r; asm("mov.b64 %0, {%1,%2};" : "=l"(r) : "f"(lo), "f"(hi)); return r;
}
__device__ __forceinline__ ull fma2(ull a, ull b, ull c) {
    ull d; asm("fma.rn.f32x2 %0, %1, %2, %3;" : "=l"(d) : "l"(a), "l"(b), "l"(c)); return d;
}
__device__ __forceinline__ float2 upk2(ull v) {
    float2 f; asm("mov.b64 {%0,%1}, %2;" : "=f"(f.x), "=f"(f.y) : "l"(v)); return f;
}

// ---------------- conv1 (im2col GEMM) + BN1 + prep fold (at fma2 floor) ---------
__global__ __launch_bounds__(128, 3)
void conv1_gemm(const float* __restrict__ x,
                const float* __restrict__ c1w,
                const float* __restrict__ c1b,
                const float* __restrict__ bn1g,
                const float* __restrict__ bn1b,
                const float* __restrict__ bn1m,
                const float* __restrict__ bn1v,
                const float* __restrict__ c2w,
                const float* __restrict__ d1w,
                const float* __restrict__ bn2g,
                const float* __restrict__ bn2v)
{
    __shared__ __align__(16) float As[2][16][64];
    __shared__ __align__(16) float Bs[2][16][128];
    const int tid  = threadIdx.x;
    const int lane = tid & 31;
    const int w    = tid >> 5;
    const int mBase = blockIdx.x * 64;
    const int nBase = blockIdx.y * 128;

    if (blockIdx.y == 0) {
        int gid = blockIdx.x * 128 + tid;
        for (int i = gid; i < COUTC * 3 * COUTC; i += 504 * 128) {
            int row = i >> 8, jj = i & 255;
            int ci = row / 3, k = row - 3 * ci;
            int co = (jj >> 1) + 128 * (jj & 1);
            g_c2wt[i] = c2w[(co * COUTC + ci) * 3 + k];
        }
        for (int i = gid; i < COUTC * COUTC; i += 504 * 128) {
            int c = i >> 8, o = i & 255;
            g_d1wt[i] = d1w[o * COUTC + c];
        }
        if (gid < COUTC)
            g_bn2a[gid] = bn2g[gid] / sqrtf(bn2v[gid] + 1e-5f);
    }

    const int warp_m = (w & 1) * 32;
    const int warp_n = (w >> 1) * 64;
    const int g = lane >> 3;
    const int j = lane & 7;

    const int am = tid & 63;
    const int kq = (tid >> 6) * 8;
    const int m_row = mBase + am;
    const int n_idx = m_row / TT;
    const int t_idx = m_row - n_idx * TT;
    const float* xrow = x + ((size_t)n_idx * CIN) * LIN + t_idx * STR1;
    const float* wrow = c1w + (size_t)(nBase + tid) * KTOT;

    ull acc[8][4];
    #pragma unroll
    for (int i = 0; i < 8; i++)
        #pragma unroll
        for (int q = 0; q < 4; q++) acc[i][q] = 0ULL;

    float4 ap0, ap1, bq0, bq1, bq2, bq3;

    #define LOAD_REGS(KB) {                                                    \
        int col = (KB) + kq;                                                   \
        const float* abase = xrow + (size_t)(col >> 5) * LIN + (col & 31);     \
        ap0 = *(const float4*)(abase);                                         \
        ap1 = *(const float4*)(abase + 4);                                     \
        bq0 = *(const float4*)(wrow + (KB));                                   \
        bq1 = *(const float4*)(wrow + (KB) + 4);                               \
        bq2 = *(const float4*)(wrow + (KB) + 8);                               \
        bq3 = *(const float4*)(wrow + (KB) + 12);                              \
    }
    #define STORE_SMEM(B) {                                                    \
        As[B][kq + 0][am] = ap0.x; As[B][kq + 1][am] = ap0.y;                  \
        As[B][kq + 2][am] = ap0.z; As[B][kq + 3][am] = ap0.w;                  \
        As[B][kq + 4][am] = ap1.x; As[B][kq + 5][am] = ap1.y;                  \
        As[B][kq + 6][am] = ap1.z; As[B][kq + 7][am] = ap1.w;                  \
        Bs[B][0][tid]  = bq0.x; Bs[B][1][tid]  = bq0.y;                        \
        Bs[B][2][tid]  = bq0.z; Bs[B][3][tid]  = bq0.w;                        \
        Bs[B][4][tid]  = bq1.x; Bs[B][5][tid]  = bq1.y;                        \
        Bs[B][6][tid]  = bq1.z; Bs[B][7][tid]  = bq1.w;                        \
        Bs[B][8][tid]  = bq2.x; Bs[B][9][tid]  = bq2.y;                        \
        Bs[B][10][tid] = bq2.z; Bs[B][11][tid] = bq2.w;                        \
        Bs[B][12][tid] = bq3.x; Bs[B][13][tid] = bq3.y;                        \
        Bs[B][14][tid] = bq3.z; Bs[B][15][tid] = bq3.w;                        \
    }

    LOAD_REGS(0);
    STORE_SMEM(0);
    __syncthreads();

    int buf = 0;
    for (int kb = 0; kb < KTOT; kb += 16) {
        const bool more = (kb + 16) < KTOT;
        if (more) LOAD_REGS(kb + 16);

        const float (*A)[64]  = As[buf];
        const float (*B)[128] = Bs[buf];
        #pragma unroll
        for (int kk = 0; kk < 16; kk++) {
            float4 x0 = *(const float4*)&A[kk][warp_m + 4 * g];
            float4 x1 = *(const float4*)&A[kk][warp_m + 16 + 4 * g];
            ulonglong2 n0 = *(const ulonglong2*)&B[kk][warp_n + 4 * j];
            ulonglong2 n1 = *(const ulonglong2*)&B[kk][warp_n + 32 + 4 * j];
            ull ap;
            #define FMA_ROW(I, AV)                        \
                ap = pk2(AV, AV);                         \
                acc[I][0] = fma2(ap, n0.x, acc[I][0]);    \
                acc[I][1] = fma2(ap, n0.y, acc[I][1]);    \
                acc[I][2] = fma2(ap, n1.x, acc[I][2]);    \
                acc[I][3] = fma2(ap, n1.y, acc[I][3]);
            FMA_ROW(0, x0.x) FMA_ROW(1, x0.y) FMA_ROW(2, x0.z) FMA_ROW(3, x0.w)
            FMA_ROW(4, x1.x) FMA_ROW(5, x1.y) FMA_ROW(6, x1.z) FMA_ROW(7, x1.w)
            #undef FMA_ROW
        }
        if (more) STORE_SMEM(buf ^ 1);
        __syncthreads();
        buf ^= 1;
    }
    #undef LOAD_REGS
    #undef STORE_SMEM

    float sc[8], bb[8], mm[8], cb[8];
    #pragma unroll
    for (int jj = 0; jj < 8; jj++) {
        int co = nBase + warp_n + ((jj < 4) ? (4 * j + jj) : (32 + 4 * j + jj - 4));
        sc[jj] = bn1g[co] / sqrtf(bn1v[co] + 1e-5f);
        bb[jj] = bn1b[co]; mm[jj] = bn1m[co]; cb[jj] = c1b[co];
    }
    #pragma unroll
    for (int i = 0; i < 8; i++) {
        int m = mBase + warp_m + ((i < 4) ? (4 * g + i) : (16 + 4 * g + i - 4));
        float o_[8];
        #pragma unroll
        for (int q = 0; q < 4; q++) {
            float2 v = upk2(acc[i][q]);
            o_[2 * q] = v.x; o_[2 * q + 1] = v.y;
        }
        #pragma unroll
        for (int jj = 0; jj < 8; jj++) {
            float t1 = (o_[jj] + cb[jj]) - mm[jj];
            o_[jj] = fmaf(t1, sc[jj], bb[jj]);
        }
        float* dst = g_z1 + (size_t)m * COUTC + nBase + warp_n;
        *(float4*)(dst + 4 * j)      = make_float4(o_[0], o_[1], o_[2], o_[3]);
        *(float4*)(dst + 32 + 4 * j) = make_float4(o_[4], o_[5], o_[6], o_[7]);
    }
}

// ---------------- conv2 + BN2 + encoder LIF : grid (n, co-half), 2 CTA/SM -------
__global__ __launch_bounds__(256, 2)
void conv2lif_kernel(const float* __restrict__ c2b,
                     const float* __restrict__ bn2b,
                     const float* __restrict__ bn2m)
{
    extern __shared__ float sm[];
    float* zt   = sm;                   // transposed z: [ci][ZTW], float idx = t+1
    float* bufA = sm + COUTC * ZTW;     // [128][BSTR]

    const int n    = blockIdx.x;
    const int half = blockIdx.y;
    const int tid  = threadIdx.x;
    const int cog  = tid & 63;
    const int th   = tid >> 6;          // 0..3
    const int t0   = th * 16;
    const int p    = half * 64 + cog;   // weight pair index (co=p, co=p+128)

    // ---- zero + fill transposed z (thread = ci, walks t; gmem coalesced) ----
    {
        float4* z4 = (float4*)zt;
        for (int i = tid; i < COUTC * ZTW / 4; i += 256) z4[i] = make_float4(0, 0, 0, 0);
        __syncthreads();
        const float* src = g_z1 + (size_t)n * (TT * COUTC) + tid;
        float* dst = zt + tid * ZTW + 1;
        #pragma unroll 7
        for (int t = 0; t < TT; t++) dst[t] = src[t * COUTC];
    }
    __syncthreads();

    // ---- conv2: fp32x2 lanes = (co, co+128); z via broadcast LDS ----
    ull acc[16];
    #pragma unroll
    for (int t = 0; t < 16; t++) acc[t] = 0ULL;
    {
        const ull* wb = (const ull*)g_c2wt;
        ull w0 = wb[p], w1 = wb[128 + p], w2 = wb[256 + p];
        #pragma unroll 2
        for (int ci = 0; ci < COUTC; ci++) {
            const int cin = (ci + 1) & 255;
            const ull* wn = wb + cin * 384;
            ull nw0 = wn[p], nw1 = wn[128 + p], nw2 = wn[256 + p];

            const float* zb = zt + ci * ZTW + t0;     // float idx t0+j == t0-1+j (+1)
            float4 f0 = *(const float4*)(zb);
            float4 f1 = *(const float4*)(zb + 4);
            float4 f2 = *(const float4*)(zb + 8);
            float4 f3 = *(const float4*)(zb + 12);
            float2 f4 = *(const float2*)(zb + 16);
            float zr[18] = {f0.x, f0.y, f0.z, f0.w, f1.x, f1.y, f1.z, f1.w,
                            f2.x, f2.y, f2.z, f2.w, f3.x, f3.y, f3.z, f3.w,
                            f4.x, f4.y};
            ull zz[18];
            #pragma unroll
            for (int jj = 0; jj < 18; jj++) zz[jj] = pk2(zr[jj], zr[jj]);
            #pragma unroll
            for (int t = 0; t < 16; t++) {
                acc[t] = fma2(w0, zz[t],     acc[t]);
                acc[t] = fma2(w1, zz[t + 1], acc[t]);
                acc[t] = fma2(w2, zz[t + 2], acc[t]);
            }
            w0 = nw0; w1 = nw1; w2 = nw2;
        }
    }
    // ---- BN2 epilogue into bufA (local rows: cog -> coA, 64+cog -> coB) ----
    {
        const int coA = half * 64 + cog, coB = coA + 128;
        const float cbA = c2b[coA], mA = bn2m[coA], sA = g_bn2a[coA], bA = bn2b[coA];
        const float cbB = c2b[coB], mB = bn2m[coB], sB = g_bn2a[coB], bB = bn2b[coB];
        #pragma unroll
        for (int t = 0; t < 16; t++) {
            float2 v = upk2(acc[t]);
            int tt = t0 + t;                    // tt=63 dummy, zeroed after LIF
            bufA[cog * BSTR + tt]        = fmaf((v.x + cbA) - mA, sA, bA);
            bufA[(64 + cog) * BSTR + tt] = fmaf((v.y + cbB) - mB, sB, bB);
        }
    }
    __syncthreads();

    // ---- encoder CUBA LIF (128 rows, per-co independent) ----
    if (tid < 128) {
        float* row = bufA + tid * BSTR;
        const float cd = (float)(1.0 - 0.9);
        const float vd = (float)(1.0 - 0.9);
        float cur = 0.0f, vol = 0.0f;
        #pragma unroll 1
        for (int t = 0; t < TT; t++) {
            float xv = row[t];
            cur = fmaf(cd, cur, xv);
            vol = fmaf(vd, vol, cur);
            float s = ((vol - 0.3f) >= 0.0f) ? 1.0f : 0.0f;
            row[t] = s;
            vol = vol * (1.0f - s);
        }
        row[TT] = 0.0f;
    }
    __syncthreads();

    // ---- copy spikes to gmem [n][co][64] ----
    for (int idx = tid; idx < 128 * 64; idx += 256) {
        int r = idx >> 6, t = idx & 63;
        int co = (r < 64) ? (half * 64 + r) : (128 + half * 64 + (r - 64));
        g_spk[((size_t)n * COUTC + co) * 64 + t] = bufA[r * BSTR + t];
    }
}

// ---------------- dense1 + LIF : grid (n, o-half), 2 CTA/SM --------------------
__global__ __launch_bounds__(256, 2)
void dense1lif_kernel()
{
    extern __shared__ float sm[];
    float* spk  = sm;                   // [256][BSTR]
    float* d1sm = sm + COUTC * BSTR;    // [128][BSTR]

    const int n    = blockIdx.x;
    const int half = blockIdx.y;
    const int tid  = threadIdx.x;

    // ---- load spikes (t=63 already zero in gmem) ----
    for (int idx = tid; idx < COUTC * 64; idx += 256) {
        int c = idx >> 6, t = idx & 63;
        spk[c * BSTR + t] = g_spk[(size_t)n * COUTC * 64 + idx];
    }
    __syncthreads();

    // ---- dense1: thread (og, th) -> o = half*128+og, t in [th*32, th*32+32) ----
    {
        const int og = tid & 127;
        const int th = tid >> 7;
        const int t0 = th * 32;
        const int o  = half * 128 + og;
        ull a[16];
        #pragma unroll
        for (int pq = 0; pq < 16; pq++) a[pq] = 0ULL;

        float w = g_d1wt[o];
        #pragma unroll 2
        for (int c = 0; c < COUTC; c++) {
            const int cn = (c + 1) & 255;
            float nw = g_d1wt[cn * COUTC + o];
            ull wp = pk2(w, w);
            const ull* sp = (const ull*)(spk + c * BSTR + t0);
            #pragma unroll
            for (int pq = 0; pq < 16; pq++)
                a[pq] = fma2(wp, sp[pq], a[pq]);
            w = nw;
        }
        ull* dd = (ull*)(d1sm + og * BSTR + t0);
        #pragma unroll
        for (int pq = 0; pq < 16; pq++) dd[pq] = a[pq];
    }
    __syncthreads();

    // ---- dense1 CUBA LIF (128 rows) ----
    if (tid < 128) {
        float* row = d1sm + tid * BSTR;
        const float vdD = (float)(1.0 - 0.1);
        float vol = 0.0f;
        #pragma unroll 1
        for (int t = 0; t < TT; t++) {
            float xv = row[t];
            vol = fmaf(vdD, vol, xv);
            float s = ((vol - 0.1f) >= 0.0f) ? 1.0f : 0.0f;
            row[t] = s;
            vol = vol * (1.0f - s);
        }
        row[TT] = 0.0f;
    }
    __syncthreads();

    for (int idx = tid; idx < 128 * 64; idx += 256) {
        int r = idx >> 6, t = idx & 63;
        g_d1s[((size_t)n * COUTC + half * 128 + r) * 64 + t] = d1sm[r * BSTR + t];
    }
}

// ---------------- dense2 + LIF + output : grid n, 128 thr, gmem-direct ----------
__global__ __launch_bounds__(128, 8)
void dense2_kernel(const float* __restrict__ d2w, float* __restrict__ out)
{
    __shared__ float d2b[128];
    const int n = blockIdx.x;
    const int tid = threadIdx.x;

    if (tid < NCLS * TT) {
        int cls = tid / TT, t = tid - cls * TT;
        const float* w  = d2w + cls * COUTC;
        const float* sp = g_d1s + (size_t)n * COUTC * 64 + t;
        float a = 0.0f;
        #pragma unroll 8
        for (int c = 0; c < COUTC; c++)
            a = fmaf(__ldg(w + c), __ldg(sp + c * 64), a);
        d2b[tid] = a;
    }
    __syncthreads();

    if (tid < NCLS) {
        const float vdD = (float)(1.0 - 0.1);
        float vol = 0.0f;
        const float* rowi = d2b + tid * TT;
        float* rowo = out + (size_t)n * (NCLS * TT) + tid * TT;
        #pragma unroll 1
        for (int t = 0; t < TT; t++) {
            float xv = rowi[t];
            vol = fmaf(vdD, vol, xv);
            float s = ((vol - 0.1f) >= 0.0f) ? 1.0f : 0.0f;
            rowo[t] = s;
            vol = vol * (1.0f - s);
        }
    }
}

// ---------------- launch ----------------
extern "C" void kernel_launch(void* const* d_in, const int* in_sizes, int n_in,
                              void* d_out, int out_size)
{
    const float* x    = (const float*)d_in[0];
    const float* c1w  = (const float*)d_in[1];
    const float* c1b  = (const float*)d_in[2];
    const float* bn1g = (const float*)d_in[3];
    const float* bn1b = (const float*)d_in[4];
    const float* bn1m = (const float*)d_in[5];
    const float* bn1v = (const float*)d_in[6];
    const float* c2w  = (const float*)d_in[7];
    const float* c2b  = (const float*)d_in[8];
    const float* bn2g = (const float*)d_in[9];
    const float* bn2b = (const float*)d_in[10];
    const float* bn2m = (const float*)d_in[11];
    const float* bn2v = (const float*)d_in[12];
    const float* d1w  = (const float*)d_in[13];
    const float* d2w  = (const float*)d_in[14];
    float* out = (float*)d_out;

    const int smemA = (COUTC * ZTW + 128 * BSTR) * (int)sizeof(float);   // 103.4 KB
    const int smemB = (COUTC * BSTR + 128 * BSTR) * (int)sizeof(float);  // 101.4 KB
    cudaFuncSetAttribute(conv2lif_kernel, cudaFuncAttributeMaxDynamicSharedMemorySize, smemA);
    cudaFuncSetAttribute(dense1lif_kernel, cudaFuncAttributeMaxDynamicSharedMemorySize, smemB);

    dim3 g1(504, 2);
    conv1_gemm<<<g1, 128>>>(x, c1w, c1b, bn1g, bn1b, bn1m, bn1v,
                            c2w, d1w, bn2g, bn2v);

    dim3 g2(BATCH, 2);
    conv2lif_kernel<<<g2, 256, smemA>>>(c2b, bn2b, bn2m);

    dense1lif_kernel<<<g2, 256, smemB>>>();

    dense2_kernel<<<BATCH, 128>>>(d2w, out);
}